// round 17
// baseline (speedup 1.0000x reference)
#include <cuda_runtime.h>
#include <cuda_bf16.h>
#include <math.h>
#include <stdint.h>

#define B_  2
#define N_  2048
#define D_  1024
#define H_  16
#define HD_ 64
#define TD_ 3072          // 3*D
#define M_  4096          // B*N
#define KP_ 3072          // split-bf16 expanded K (3 * 1024)
#define NKT 96            // KP_/32 k-tiles
#define KQW 1536          // KP_/2 packed words per row

// ---------------- device scratch (globals: allocation-rule safe) -----------
__device__ float g_qkv[(size_t)M_ * TD_];              // 50 MB fp32 qkv
__device__ float g_cp [B_ * H_ * N_];                  // coord_proj
__device__ uint32_t g_A16[(size_t)M_  * KQW];          // packed A'  [m][1536w]
__device__ uint32_t g_B16[(size_t)TD_ * KQW];          // packed B'^T [n][1536w]
__device__ uint32_t g_Kp[(size_t)32 * 2048 * 64];      // 16 MB packed K'
__device__ uint32_t g_Vt[(size_t)32 * 32 * 64 * 64];   // 16 MB packed V'^T

// ---------------------------------------------------------------------------
__device__ __forceinline__ void mma16816(float* c, const uint32_t* a,
                                         const uint32_t* b)
{
    asm volatile(
        "mma.sync.aligned.m16n8k16.row.col.f32.bf16.bf16.f32 "
        "{%0,%1,%2,%3}, {%4,%5,%6,%7}, {%8,%9}, {%0,%1,%2,%3};"
        : "+f"(c[0]), "+f"(c[1]), "+f"(c[2]), "+f"(c[3])
        : "r"(a[0]), "r"(a[1]), "r"(a[2]), "r"(a[3]), "r"(b[0]), "r"(b[1]));
}
__device__ __forceinline__ uint32_t packbf(float lo, float hi)
{
    uint32_t r;
    asm("cvt.rn.bf16x2.f32 %0, %1, %2;" : "=r"(r) : "f"(hi), "f"(lo));
    return r;
}
__device__ __forceinline__ void packsplit(float a, float b,
                                          uint32_t& hw, uint32_t& lw)
{
    uint32_t h = packbf(a, b);
    float ra = a - __uint_as_float(h << 16);
    float rb = b - __uint_as_float(h & 0xffff0000u);
    hw = h;
    lw = packbf(ra, rb);
}
// word permutation: fragment words (qp, qp+4) -> adjacent (2qp, 2qp+1)
__device__ __forceinline__ int permw(int p)
{
    int j = p & 7;
    return (p >> 3) * 8 + (((j & 3) << 1) | (j >> 2));
}

// ---------------------------------------------------------------------------
// A' conversion -> permuted pair-packed words [m][1536w]
// thread = (m, 8 consecutive k') = 4 pair-words.
// ---------------------------------------------------------------------------
__global__ __launch_bounds__(256)
void conv_a_kernel(const float* __restrict__ x)
{
    int idx = blockIdx.x * 256 + threadIdx.x;
    int m   = idx / 384;
    int g   = idx - m * 384;
    int kp0 = g * 8;
    int kk0 = kp0 & 1023;
    bool lo_region = (kp0 >= 1024) && (kp0 < 2048);

    float4 v0 = *(const float4*)(x + (size_t)m * 1024 + kk0);
    float4 v1 = *(const float4*)(x + (size_t)m * 1024 + kk0 + 4);
    float vv[8] = {v0.x, v0.y, v0.z, v0.w, v1.x, v1.y, v1.z, v1.w};

    uint16_t o[8];
#pragma unroll
    for (int t = 0; t < 8; t++) {
        __nv_bfloat16 h = __float2bfloat16(vv[t]);
        if (lo_region) h = __float2bfloat16(vv[t] - __bfloat162float(h));
        o[t] = __bfloat16_as_ushort(h);
    }
    int p0 = kp0 >> 1;
    uint32_t* dst = g_A16 + (size_t)m * KQW;
#pragma unroll
    for (int j = 0; j < 4; j++)
        dst[permw(p0 + j)] = ((uint32_t)o[2 * j + 1] << 16) | o[2 * j];
}

__global__ __launch_bounds__(256)
void conv_b_kernel(const float* __restrict__ W)
{
    int wid  = threadIdx.x >> 5;
    int lane = threadIdx.x & 31;
    int gw   = blockIdx.x * 8 + wid;
    int g    = gw / 96;
    int n    = (gw - g * 96) * 32 + lane;
    int kp0  = g * 8;
    int kk0  = kp0 & 1023;
    bool lo_region = (kp0 >= 2048);

    uint16_t o[8];
#pragma unroll
    for (int t = 0; t < 8; t++) {
        float w = __ldg(W + (size_t)(kk0 + t) * TD_ + n);
        __nv_bfloat16 h = __float2bfloat16(w);
        if (lo_region) h = __float2bfloat16(w - __bfloat162float(h));
        o[t] = __bfloat16_as_ushort(h);
    }
    int p0 = kp0 >> 1;
    uint32_t* dst = g_B16 + (size_t)n * KQW;
#pragma unroll
    for (int j = 0; j < 4; j++)
        dst[permw(p0 + j)] = ((uint32_t)o[2 * j + 1] << 16) | o[2 * j];
}

// ---------------------------------------------------------------------------
// QKV GEMM via mma.sync with pair-packed operands.
// smem rows: 16 words (32 k') + 8 pad = stride 24 -> conflict-free LDS.64.
// ---------------------------------------------------------------------------
__global__ __launch_bounds__(256)
void qkv_mma_kernel(const float* __restrict__ bias)
{
    __shared__ uint32_t As[2][128 * 24];
    __shared__ uint32_t Bs[2][128 * 24];

    const int tid  = threadIdx.x;
    const int wid  = tid >> 5;
    const int lane = tid & 31;
    const int grp  = lane >> 2;
    const int qp   = lane & 3;
    const int mb   = blockIdx.y;
    const int nb   = blockIdx.x;
    const int m0   = (wid >> 1) * 32;
    const int n0w  = (wid & 1) * 64;

    const uint32_t* gA = g_A16 + (size_t)(mb * 128) * KQW;
    const uint32_t* gB = g_B16 + (size_t)(nb * 128) * KQW;

    float acc[2][8][4];
#pragma unroll
    for (int mt = 0; mt < 2; mt++)
#pragma unroll
        for (int nt = 0; nt < 8; nt++)
#pragma unroll
            for (int i = 0; i < 4; i++) acc[mt][nt][i] = 0.f;

    // loader mapping: 512 uint4 per operand tile; 2 per thread
    // i = tid*2+p : row = i>>2 (0..127), q = i&3 (uint4 within 16-word row)
#pragma unroll
    for (int p = 0; p < 2; p++) {
        int i = tid * 2 + p;
        int row = i >> 2, q = i & 3;
        *(uint4*)&As[0][row * 24 + q * 4] =
            *(const uint4*)&gA[(size_t)row * KQW + q * 4];
        *(uint4*)&Bs[0][row * 24 + q * 4] =
            *(const uint4*)&gB[(size_t)row * KQW + q * 4];
    }
    __syncthreads();

    for (int kt = 0; kt < NKT; kt++) {
        const int cur = kt & 1;
        uint4 av[2], bv[2];
        if (kt + 1 < NKT) {
            int kw = (kt + 1) * 16;
#pragma unroll
            for (int p = 0; p < 2; p++) {
                int i = tid * 2 + p;
                int row = i >> 2, q = i & 3;
                av[p] = *(const uint4*)&gA[(size_t)row * KQW + kw + q * 4];
                bv[p] = *(const uint4*)&gB[(size_t)row * KQW + kw + q * 4];
            }
        }
#pragma unroll
        for (int ks = 0; ks < 2; ks++) {
            const int ko = ks * 8 + qp * 2;
            uint32_t a[2][4];
#pragma unroll
            for (int mt = 0; mt < 2; mt++) {
                int r = m0 + mt * 16 + grp;
                uint2 A0 = *(const uint2*)&As[cur][r * 24 + ko];
                uint2 A1 = *(const uint2*)&As[cur][(r + 8) * 24 + ko];
                a[mt][0] = A0.x; a[mt][1] = A1.x;
                a[mt][2] = A0.y; a[mt][3] = A1.y;
            }
#pragma unroll
            for (int nt = 0; nt < 8; nt++) {
                int nr = n0w + nt * 8 + grp;
                uint2 bv2 = *(const uint2*)&Bs[cur][nr * 24 + ko];
                uint32_t b[2] = { bv2.x, bv2.y };
#pragma unroll
                for (int mt = 0; mt < 2; mt++)
                    mma16816(acc[mt][nt], a[mt], b);
            }
        }
        if (kt + 1 < NKT) {
#pragma unroll
            for (int p = 0; p < 2; p++) {
                int i = tid * 2 + p;
                int row = i >> 2, q = i & 3;
                *(uint4*)&As[cur ^ 1][row * 24 + q * 4] = av[p];
                *(uint4*)&Bs[cur ^ 1][row * 24 + q * 4] = bv[p];
            }
            __syncthreads();
        }
    }

#pragma unroll
    for (int mt = 0; mt < 2; mt++) {
        int row = mb * 128 + m0 + mt * 16 + grp;
#pragma unroll
        for (int nt = 0; nt < 8; nt++) {
            int col = nb * 128 + n0w + nt * 8 + qp * 2;
            float bx = __ldg(bias + col);
            float by = __ldg(bias + col + 1);
            float2 v0 = { acc[mt][nt][0] + bx, acc[mt][nt][1] + by };
            float2 v1 = { acc[mt][nt][2] + bx, acc[mt][nt][3] + by };
            *(float2*)&g_qkv[(size_t)row * TD_ + col] = v0;
            *(float2*)&g_qkv[(size_t)(row + 8) * TD_ + col] = v1;
        }
    }
}

// ---------------------------------------------------------------------------
__global__ void coord_kernel(const float* __restrict__ coords,
                             const float* __restrict__ rw)
{
    int idx = blockIdx.x * blockDim.x + threadIdx.x;
    if (idx >= B_ * H_ * N_) return;
    int n = idx % N_;
    int h = (idx / N_) % H_;
    int b = idx / (N_ * H_);
    const float* c = coords + ((size_t)b * N_ + n) * 3;
    const float* w = rw + h * 3;
    g_cp[idx] = c[0] * w[0] + c[1] * w[1] + c[2] * w[2];
}

// ---------------------------------------------------------------------------
// K/V pre-conversion (unchanged, proven)
// ---------------------------------------------------------------------------
__global__ __launch_bounds__(128)
void conv_kv_kernel()
{
    __shared__ float VF[64 * 68];

    const int kt  = blockIdx.x;          // 32
    const int bh  = blockIdx.y;          // 32
    const int b   = bh >> 4;
    const int h   = bh & 15;
    const int tid = threadIdx.x;
    const int k0  = kt * 64;

    const float* hb = g_qkv + (size_t)(b * N_) * TD_ + h * HD_;
    uint32_t* Kp = g_Kp + ((size_t)bh * 2048 + k0) * 64;

#pragma unroll
    for (int p = 0; p < 8; p++) {
        int idx = p * 128 + tid;
        int row = idx >> 4;
        int c4  = (idx & 15) << 2;
        const float* src = hb + (size_t)(k0 + row) * TD_ + c4;
        float4 kv = *(const float4*)(src + 1024);
        uint32_t h0, l0, h1, l1;
        packsplit(kv.x, kv.y, h0, l0);
        packsplit(kv.z, kv.w, h1, l1);
        int p0 = c4 >> 1;
        uint32_t* r = Kp + row * 64;
        r[permw(p0)]          = h0;
        r[permw(p0 + 1)]      = h1;
        r[32 + permw(p0)]     = l0;
        r[32 + permw(p0 + 1)] = l1;
        float4 vv = *(const float4*)(src + 2048);
        *(float4*)&VF[row * 68 + ((((c4 >> 2) ^ (row & 15))) << 2)] = vv;
    }
    __syncthreads();

    {
        int d  = tid & 63;
        int kh = tid >> 6;
        uint32_t* Vt = g_Vt + (((size_t)bh * 32 + kt) * 64 + d) * 64;
#pragma unroll
        for (int i = 0; i < 16; i++) {
            int k = kh * 32 + 2 * i;
            float f0 = VF[k * 68 + ((((d >> 2) ^ (k & 15))) << 2) + (d & 3)];
            float f1 = VF[(k + 1) * 68 + ((((d >> 2) ^ ((k + 1) & 15))) << 2) + (d & 3)];
            uint32_t hw, lw;
            packsplit(f0, f1, hw, lw);
            int pi = kh * 16 + i;
            Vt[permw(pi)]      = hw;
            Vt[32 + permw(pi)] = lw;
        }
    }
}

// ---------------------------------------------------------------------------
// Flash attention on tensor cores (unchanged from round 12, proven at 776us)
// ---------------------------------------------------------------------------
#define QS_OFF 0
#define KS_OFF 4608
#define VT_OFF 9216
#define AT_SMEM_WORDS (VT_OFF + 64 * 72)   // 13824 words = 55296 B

__global__ __launch_bounds__(128)
void attn_tc_kernel(const float* __restrict__ bias2d, float* __restrict__ out)
{
    extern __shared__ uint32_t smw[];
    uint32_t* QS = smw + QS_OFF;
    uint32_t* KS = smw + KS_OFF;
    uint32_t* VT = smw + VT_OFF;

    const int tid  = threadIdx.x;
    const int wid  = tid >> 5;
    const int lane = tid & 31;
    const int grp  = lane >> 2;
    const int qp   = lane & 3;
    const int bh   = blockIdx.y;
    const int b    = bh >> 4;
    const int h    = bh & 15;
    const int q0   = blockIdx.x * 64;

    const float* hb  = g_qkv + (size_t)(b * N_) * TD_ + h * HD_;
    const float* cpb = g_cp + (size_t)bh * N_;

#pragma unroll
    for (int p = 0; p < 8; p++) {
        int idx = p * 128 + tid;
        int row = idx >> 4;
        int c4  = (idx & 15) << 2;
        float4 v = *(const float4*)(hb + (size_t)(q0 + row) * TD_ + c4);
        v.x *= 0.125f; v.y *= 0.125f; v.z *= 0.125f; v.w *= 0.125f;
        uint32_t h0, l0, h1, l1;
        packsplit(v.x, v.y, h0, l0);
        packsplit(v.z, v.w, h1, l1);
        int p0 = c4 >> 1;
        uint32_t* r = QS + row * 72;
        r[permw(p0)]          = h0;
        r[permw(p0 + 1)]      = h1;
        r[32 + permw(p0)]     = l0;
        r[32 + permw(p0 + 1)] = l1;
    }

    float Oacc[8][4];
#pragma unroll
    for (int nt = 0; nt < 8; nt++)
#pragma unroll
        for (int i = 0; i < 4; i++) Oacc[nt][i] = 0.f;
    float m0 = -1e30f, m1 = -1e30f, l0s = 0.f, l1s = 0.f;

    const float* brow0 = bias2d + (size_t)(q0 + 16 * wid + grp) * N_;
    const float* brow1 = brow0 + 8 * N_;

    const uint32_t* gKbh = g_Kp + (size_t)bh * 2048 * 64;
    const uint32_t* gVbh = g_Vt + (size_t)bh * 32 * 64 * 64;

    for (int k0 = 0; k0 < N_; k0 += 64) {
        __syncthreads();

        const uint32_t* gK = gKbh + (size_t)k0 * 64;
        const uint32_t* gV = gVbh + (size_t)(k0 >> 6) * 64 * 64;
#pragma unroll
        for (int p = 0; p < 8; p++) {
            int idx = p * 128 + tid;
            int row = idx >> 4;
            int w4  = (idx & 15) << 2;
            *(uint4*)&KS[row * 72 + w4] = *(const uint4*)&gK[row * 64 + w4];
            *(uint4*)&VT[row * 72 + w4] = *(const uint4*)&gV[row * 64 + w4];
        }
        __syncthreads();

        float S[8][4];
#pragma unroll
        for (int nt = 0; nt < 8; nt++)
#pragma unroll
            for (int i = 0; i < 4; i++) S[nt][i] = 0.f;

#pragma unroll
        for (int ck = 0; ck < 4; ck++) {
            const uint32_t* q0p = QS + (16 * wid + grp) * 72 + 8 * ck + 2 * qp;
            const uint32_t* q1p = QS + (16 * wid + grp + 8) * 72 + 8 * ck + 2 * qp;
            uint2 hA = *(const uint2*)q0p;
            uint2 hB = *(const uint2*)q1p;
            uint2 lA = *(const uint2*)(q0p + 32);
            uint2 lB = *(const uint2*)(q1p + 32);
            uint32_t ah[4] = {hA.x, hB.x, hA.y, hB.y};
            uint32_t al[4] = {lA.x, lB.x, lA.y, lB.y};
#pragma unroll
            for (int nt = 0; nt < 8; nt++) {
                const uint32_t* kp = KS + (8 * nt + grp) * 72 + 8 * ck + 2 * qp;
                uint2 bh2 = *(const uint2*)kp;
                uint2 bl2 = *(const uint2*)(kp + 32);
                uint32_t bbh[2] = {bh2.x, bh2.y};
                uint32_t bbl[2] = {bl2.x, bl2.y};
                mma16816(S[nt], ah, bbh);
                mma16816(S[nt], al, bbh);
                mma16816(S[nt], ah, bbl);
            }
        }

#pragma unroll
        for (int nt = 0; nt < 8; nt++) {
            int col = k0 + 8 * nt + 2 * qp;
            float2 cpv = *(const float2*)(cpb + col);
            float2 b0 = *(const float2*)(brow0 + col);
            float2 b1 = *(const float2*)(brow1 + col);
            S[nt][0] += b0.x - cpv.x;
            S[nt][1] += b0.y - cpv.y;
            S[nt][2] += b1.x - cpv.x;
            S[nt][3] += b1.y - cpv.y;
        }

        float mx0 = -1e30f, mx1 = -1e30f;
#pragma unroll
        for (int nt = 0; nt < 8; nt++) {
            mx0 = fmaxf(mx0, fmaxf(S[nt][0], S[nt][1]));
            mx1 = fmaxf(mx1, fmaxf(S[nt][2], S[nt][3]));
        }
        mx0 = fmaxf(mx0, __shfl_xor_sync(0xffffffffu, mx0, 1));
        mx0 = fmaxf(mx0, __shfl_xor_sync(0xffffffffu, mx0, 2));
        mx1 = fmaxf(mx1, __shfl_xor_sync(0xffffffffu, mx1, 1));
        mx1 = fmaxf(mx1, __shfl_xor_sync(0xffffffffu, mx1, 2));
        float mn0 = fmaxf(m0, mx0);
        float mn1 = fmaxf(m1, mx1);
        float a0 = __expf(m0 - mn0);
        float a1 = __expf(m1 - mn1);
        m0 = mn0; m1 = mn1;
        float rs0 = 0.f, rs1 = 0.f;
#pragma unroll
        for (int nt = 0; nt < 8; nt++) {
            S[nt][0] = __expf(S[nt][0] - mn0);
            S[nt][1] = __expf(S[nt][1] - mn0);
            S[nt][2] = __expf(S[nt][2] - mn1);
            S[nt][3] = __expf(S[nt][3] - mn1);
            rs0 += S[nt][0] + S[nt][1];
            rs1 += S[nt][2] + S[nt][3];
        }
        rs0 += __shfl_xor_sync(0xffffffffu, rs0, 1);
        rs0 += __shfl_xor_sync(0xffffffffu, rs0, 2);
        rs1 += __shfl_xor_sync(0xffffffffu, rs1, 1);
        rs1 += __shfl_xor_sync(0xffffffffu, rs1, 2);
        l0s = l0s * a0 + rs0;
        l1s = l1s * a1 + rs1;
#pragma unroll
        for (int nt = 0; nt < 8; nt++) {
            Oacc[nt][0] *= a0; Oacc[nt][1] *= a0;
            Oacc[nt][2] *= a1; Oacc[nt][3] *= a1;
        }

        uint32_t Ph[4][4], Pl[4][4];
#pragma unroll
        for (int ck = 0; ck < 4; ck++) {
            int u = 2 * ck, v = u + 1;
            packsplit(S[u][0], S[u][1], Ph[ck][0], Pl[ck][0]);
            packsplit(S[u][2], S[u][3], Ph[ck][1], Pl[ck][1]);
            packsplit(S[v][0], S[v][1], Ph[ck][2], Pl[ck][2]);
            packsplit(S[v][2], S[v][3], Ph[ck][3], Pl[ck][3]);
        }

#pragma unroll
        for (int ck = 0; ck < 4; ck++) {
#pragma unroll
            for (int nt = 0; nt < 8; nt++) {
                const uint32_t* vp = VT + (8 * nt + grp) * 72 + 8 * ck + 2 * qp;
                uint2 vh2 = *(const uint2*)vp;
                uint2 vl2 = *(const uint2*)(vp + 32);
                uint32_t bbh[2] = {vh2.x, vh2.y};
                uint32_t bbl[2] = {vl2.x, vl2.y};
                mma16816(Oacc[nt], Ph[ck], bbh);
                mma16816(Oacc[nt], Pl[ck], bbh);
                mma16816(Oacc[nt], Ph[ck], bbl);
            }
        }
    }

    float inv0 = 1.0f / l0s, inv1 = 1.0f / l1s;
    float* or0 = out + (size_t)(b * N_ + q0 + 16 * wid + grp) * D_ + h * HD_;
    float* or1 = or0 + 8 * D_;
#pragma unroll
    for (int nt = 0; nt < 8; nt++) {
        int c = 8 * nt + 2 * qp;
        float2 v0 = { Oacc[nt][0] * inv0, Oacc[nt][1] * inv0 };
        float2 v1 = { Oacc[nt][2] * inv1, Oacc[nt][3] * inv1 };
        *(float2*)(or0 + c) = v0;
        *(float2*)(or1 + c) = v1;
    }
}

// ---------------------------------------------------------------------------
extern "C" void kernel_launch(void* const* d_in, const int* in_sizes, int n_in,
                              void* d_out, int out_size)
{
    const float* x         = (const float*)d_in[0];
    const float* coords    = (const float*)d_in[1];
    const float* attn_bias = (const float*)d_in[2];
    const float* Wqkv      = (const float*)d_in[3];
    const float* bqkv      = (const float*)d_in[4];
    const float* rel_w     = (const float*)d_in[5];
    float* out = (float*)d_out;

    conv_a_kernel<<<(M_ * 384) / 256, 256>>>(x);
    conv_b_kernel<<<(TD_ / 32) * NKT * 4 / 8, 256>>>(Wqkv);

    qkv_mma_kernel<<<dim3(TD_ / 128, M_ / 128), 256>>>(bqkv);

    conv_kv_kernel<<<dim3(32, 32), 128>>>();

    coord_kernel<<<(B_ * H_ * N_ + 255) / 256, 256>>>(coords, rel_w);

    const int attn_smem = AT_SMEM_WORDS * 4;   // 55296 B
    cudaFuncSetAttribute(attn_tc_kernel,
                         cudaFuncAttributeMaxDynamicSharedMemorySize, attn_smem);
    attn_tc_kernel<<<dim3(N_ / 64, B_ * H_), 128, attn_smem>>>(attn_bias, out);
}